// round 7
// baseline (speedup 1.0000x reference)
#include <cuda_runtime.h>
#include <cuda_bf16.h>
#include <cstdint>

// ---------------------------------------------------------------------------
// Problem constants
// ---------------------------------------------------------------------------
#define BATCH   64
#define SEQ     2048
#define CIN     32
#define WIN     20
#define DIN     (WIN * CIN)      // 640
#define DP      (DIN / 2)        // 320
#define HID     128
#define G4      (4 * HID)        // 512
#define L_OUT   (SEQ - WIN)      // 2028
#define XT      2032             // padded time stride for g_xpre (mult of 8, > L_OUT+3)
#define LBL     48

// ---------------------------------------------------------------------------
// Scratch (static __device__ arrays; no cudaMalloc allowed)
// ---------------------------------------------------------------------------
__device__ float g_wc[DIN * G4];                       // combined proj->ih0 weight [d][g]
__device__ float g_bias0[G4];
__device__ float g_xpre[(size_t)BATCH * G4 * XT];      // preactivations, [b][g][t] (t-major!)
__device__ float g_hseq[(size_t)BATCH * L_OUT * HID];  // per-step hidden outputs [b][t][h]

// ---------------------------------------------------------------------------
// Packed fp32x2 helpers
// ---------------------------------------------------------------------------
__device__ __forceinline__ unsigned long long pk2(float x, float y) {
    unsigned long long r;
    asm("mov.b64 %0, {%1, %2};" : "=l"(r) : "f"(x), "f"(y));
    return r;
}
__device__ __forceinline__ float2 unpk2(unsigned long long v) {
    float2 r;
    asm("mov.b64 {%0, %1}, %2;" : "=f"(r.x), "=f"(r.y) : "l"(v));
    return r;
}
__device__ __forceinline__ void fma2(unsigned long long& d, unsigned long long a,
                                     unsigned long long b) {
    asm("fma.rn.f32x2 %0, %1, %2, %3;" : "=l"(d) : "l"(a), "l"(b), "l"(d));
}

// ---------------------------------------------------------------------------
// Cluster / mbarrier helpers
// ---------------------------------------------------------------------------
__device__ __forceinline__ unsigned smem_u32(const void* p) {
    return (unsigned)__cvta_generic_to_shared(p);
}
__device__ __forceinline__ unsigned mapa_rank(unsigned addr, unsigned rank) {
    unsigned r;
    asm("mapa.shared::cluster.u32 %0, %1, %2;" : "=r"(r) : "r"(addr), "r"(rank));
    return r;
}
__device__ __forceinline__ void mbar_init(unsigned addr, unsigned cnt) {
    asm volatile("mbarrier.init.shared.b64 [%0], %1;" :: "r"(addr), "r"(cnt) : "memory");
}
__device__ __forceinline__ void mbar_expect_tx(unsigned addr, unsigned bytes) {
    asm volatile("mbarrier.arrive.expect_tx.shared.b64 _, [%0], %1;"
                 :: "r"(addr), "r"(bytes) : "memory");
}
__device__ __forceinline__ void fence_proxy_async_cta() {
    asm volatile("fence.proxy.async.shared::cta;" ::: "memory");
}
__device__ __forceinline__ void bulk_copy_to_peer(unsigned dst_cluster, unsigned src_cta,
                                                  unsigned bytes, unsigned peer_mbar) {
    asm volatile(
        "cp.async.bulk.shared::cluster.shared::cta.mbarrier::complete_tx::bytes "
        "[%0], [%1], %2, [%3];"
        :: "r"(dst_cluster), "r"(src_cta), "r"(bytes), "r"(peer_mbar) : "memory");
}
__device__ __forceinline__ void mbar_wait_cluster(unsigned addr, unsigned parity) {
    asm volatile(
        "{\n\t"
        ".reg .pred P1;\n\t"
        "WAIT_%=:\n\t"
        "mbarrier.try_wait.parity.acquire.cluster.shared::cta.b64 P1, [%0], %1, 0x989680;\n\t"
        "@P1 bra.uni DONE_%=;\n\t"
        "bra.uni WAIT_%=;\n\t"
        "DONE_%=:\n\t"
        "}"
        :: "r"(addr), "r"(parity) : "memory");
}
__device__ __forceinline__ void cluster_barrier() {
    asm volatile("barrier.cluster.arrive.aligned;" ::: "memory");
    asm volatile("barrier.cluster.wait.aligned;" ::: "memory");
}

// ---------------------------------------------------------------------------
// Fast activations (fp32, ~1e-6 rel error)
// ---------------------------------------------------------------------------
__device__ __forceinline__ float fast_sigmoid(float x) {
    return 1.f / (1.f + __expf(-x));
}
__device__ __forceinline__ float fast_tanh(float x) {
    float ax = fabsf(x);
    float e  = __expf(-2.f * ax);
    float r  = __fdividef(1.f - e, 1.f + e);
    return copysignf(r, x);
}

// ---------------------------------------------------------------------------
// Kernel 1: fold projection into layer-0 input weight.
// ---------------------------------------------------------------------------
__global__ void combine_kernel(const float* __restrict__ proj_w,
                               const float* __restrict__ w_ih0) {
    __shared__ float sPW[32][32];
    __shared__ float sWI[32][33];
    int tx = threadIdx.x, ty = threadIdx.y;
    int d0 = blockIdx.x * 32, g0 = blockIdx.y * 32;
    float acc = 0.f;
    for (int p0 = 0; p0 < DP; p0 += 32) {
        sPW[ty][tx] = proj_w[(size_t)(p0 + ty) * DIN + d0 + tx];
        sWI[ty][tx] = w_ih0[(size_t)(g0 + ty) * DP + p0 + tx];
        __syncthreads();
#pragma unroll
        for (int p = 0; p < 32; p++) acc += sPW[p][tx] * sWI[ty][p];
        __syncthreads();
    }
    g_wc[(size_t)(d0 + tx) * G4 + g0 + ty] = acc;
}

__global__ void bias0_kernel(const float* __restrict__ proj_b,
                             const float* __restrict__ w_ih0,
                             const float* __restrict__ b_ih0,
                             const float* __restrict__ b_hh0) {
    int gidx = threadIdx.x;
    float acc = b_ih0[gidx] + b_hh0[gidx];
    const float* wr = w_ih0 + (size_t)gidx * DP;
    for (int p = 0; p < DP; p++) acc += proj_b[p] * wr[p];
    g_bias0[gidx] = acc;
}

// ---------------------------------------------------------------------------
// Kernel 2: layer-0 preactivations (implicit sliding-window GEMM).
// Output transposed: g_xpre[b][g][t].
// ---------------------------------------------------------------------------
__global__ void __launch_bounds__(256)
xpre0_kernel(const float* __restrict__ in) {
    __shared__ __align__(16) float sIn[128 * 32 + DIN];
    __shared__ __align__(16) float sB[32][64];

    int tid = threadIdx.x;
    int tx = tid & 15, ty = tid >> 4;
    int t0 = blockIdx.x * 128;
    int n0 = blockIdx.y * 64;
    int b  = blockIdx.z;

    const float* inb = in + (size_t)b * SEQ * CIN;
    int base = t0 * CIN;
    for (int i = tid; i < 128 * 32 + DIN; i += 256) {
        int gi = base + i;
        sIn[i] = (gi < SEQ * CIN) ? inb[gi] : 0.f;
    }
    __syncthreads();

    unsigned long long acc[8][2];
#pragma unroll
    for (int i = 0; i < 8; i++) { acc[i][0] = pk2(0.f, 0.f); acc[i][1] = pk2(0.f, 0.f); }

    for (int k0 = 0; k0 < DIN; k0 += 32) {
#pragma unroll
        for (int r = 0; r < 2; r++) {
            int j = tid * 8 + r * 4;
            int kk = j >> 6, nn = j & 63;
            *(float4*)&sB[kk][nn] =
                *(const float4*)&g_wc[(size_t)(k0 + kk) * G4 + n0 + nn];
        }
        __syncthreads();
#pragma unroll
        for (int k = 0; k < 32; k++) {
            ulonglong2 bb = *(const ulonglong2*)&sB[k][tx * 4];
#pragma unroll
            for (int i = 0; i < 8; i++) {
                float a = sIn[(ty * 8 + i) * CIN + k0 + k];
                unsigned long long aa = pk2(a, a);
                fma2(acc[i][0], aa, bb.x);
                fma2(acc[i][1], aa, bb.y);
            }
        }
        __syncthreads();
    }

    float4 bias = *(const float4*)&g_bias0[n0 + tx * 4];
    int tbase = t0 + ty * 8;
    if (tbase < XT) {
#pragma unroll
        for (int nn = 0; nn < 4; nn++) {
            float bv = (nn == 0) ? bias.x : (nn == 1) ? bias.y : (nn == 2) ? bias.z : bias.w;
            float v[8];
#pragma unroll
            for (int i = 0; i < 8; i++) {
                float2 p = unpk2(acc[i][nn >> 1]);
                v[i] = ((nn & 1) ? p.y : p.x) + bv;
            }
            float* dst = &g_xpre[((size_t)b * G4 + n0 + tx * 4 + nn) * XT + tbase];
            *(float4*)(dst)     = make_float4(v[0], v[1], v[2], v[3]);
            *(float4*)(dst + 4) = make_float4(v[4], v[5], v[6], v[7]);
        }
    }
}

// ---------------------------------------------------------------------------
// Kernel 3: input preactivations for layers 1..3 (transposed output).
// ---------------------------------------------------------------------------
__global__ void __launch_bounds__(256)
gemm_ih_kernel(const float* __restrict__ w_ih,
               const float* __restrict__ b_ih,
               const float* __restrict__ b_hh) {
    __shared__ __align__(16) float sA[64 * 64];
    __shared__ __align__(16) float sB[64 * 68];

    int tid = threadIdx.x;
    int tx = tid & 15, ty = tid >> 4;
    int t0 = blockIdx.x * 64;
    int n0 = blockIdx.y * 64;
    int b  = blockIdx.z;

    unsigned long long acc[4][2];
#pragma unroll
    for (int i = 0; i < 4; i++) { acc[i][0] = pk2(0.f, 0.f); acc[i][1] = pk2(0.f, 0.f); }

    for (int kt = 0; kt < 2; kt++) {
#pragma unroll
        for (int r = 0; r < 4; r++) {
            int j = tid * 16 + r * 4;
            int row = j >> 6, col = j & 63;
            int t = t0 + row;
            float4 v = make_float4(0.f, 0.f, 0.f, 0.f);
            if (t < L_OUT)
                v = *(const float4*)&g_hseq[((size_t)b * L_OUT + t) * HID + kt * 64 + col];
            *(float4*)&sA[row * 64 + col] = v;
        }
        for (int j = tid; j < 64 * 64; j += 256) {
            int n = j >> 6, kk = j & 63;
            sB[kk * 68 + n] = w_ih[(size_t)(n0 + n) * HID + kt * 64 + kk];
        }
        __syncthreads();
#pragma unroll
        for (int k = 0; k < 64; k++) {
            ulonglong2 bb = *(const ulonglong2*)&sB[k * 68 + tx * 4];
#pragma unroll
            for (int i = 0; i < 4; i++) {
                float a = sA[(ty * 4 + i) * 64 + k];
                unsigned long long aa = pk2(a, a);
                fma2(acc[i][0], aa, bb.x);
                fma2(acc[i][1], aa, bb.y);
            }
        }
        __syncthreads();
    }

    int n = n0 + tx * 4;
    float4 bias = make_float4(b_ih[n] + b_hh[n], b_ih[n + 1] + b_hh[n + 1],
                              b_ih[n + 2] + b_hh[n + 2], b_ih[n + 3] + b_hh[n + 3]);
    int tbase = t0 + ty * 4;
    if (tbase < XT) {
#pragma unroll
        for (int nn = 0; nn < 4; nn++) {
            float bv = (nn == 0) ? bias.x : (nn == 1) ? bias.y : (nn == 2) ? bias.z : bias.w;
            float v[4];
#pragma unroll
            for (int i = 0; i < 4; i++) {
                float2 p = unpk2(acc[i][nn >> 1]);
                v[i] = ((nn & 1) ? p.y : p.x) + bv;
            }
            float* dst = &g_xpre[((size_t)b * G4 + n + nn) * XT + tbase];
            *(float4*)(dst) = make_float4(v[0], v[1], v[2], v[3]);
        }
    }
}

// ---------------------------------------------------------------------------
// Kernel 4: recurrent scan — R6 bulk-exchange protocol, now processing TWO
// batch elements per cluster (same weights, two independent recurrences).
// The per-step fixed latency (bulk transit + mbarrier wake + 2 syncthreads)
// is paid once for 2 timesteps of work; both streams' 2x256 gate floats
// cross the cluster in ONE 2 KB cp.async.bulk per step.
//
// Grid: 32 clusters x 2 CTAs. Cluster cid handles b0=cid, b1=cid+32.
// Thread tid: gate row g = rank*256+tid (shared by both streams).
// Phase/parity protocol identical to R6 (validated): one bar pair,
// expect_tx(2048) each step, wait bar[t&1] parity (t>>1)&1.
// ---------------------------------------------------------------------------
__global__ void __cluster_dims__(2, 1, 1) __launch_bounds__(256, 1)
scan_kernel(const float* __restrict__ w_hh) {
    __shared__ __align__(16) float h_sh[2][HID];     // [stream][unit]
    __shared__ __align__(16) float stg[2][2 * 256];  // [phase][stream*256+gate]
    __shared__ __align__(16) float gr[2][2 * 256];   // remote landing
    __shared__ __align__(8) unsigned long long mbars[2];

    int tid  = threadIdx.x;
    int rank = blockIdx.x & 1;
    int cid  = blockIdx.x >> 1;
    int b0   = cid;
    int b1   = cid + (BATCH / 2);
    int g    = rank * 256 + tid;

    // recurrent weight row -> registers as f32x2 pairs (shared by streams)
    unsigned long long w2[64];
    const ulonglong2* wr = (const ulonglong2*)(w_hh + (size_t)g * HID);
#pragma unroll
    for (int k = 0; k < 32; k++) {
        ulonglong2 u = wr[k];
        w2[2 * k]     = u.x;
        w2[2 * k + 1] = u.y;
    }

    if (tid < HID) { h_sh[0][tid] = 0.f; h_sh[1][tid] = 0.f; }
    unsigned bar0 = smem_u32(&mbars[0]);
    unsigned bar1 = smem_u32(&mbars[1]);
    if (tid == 0) { mbar_init(bar0, 1); mbar_init(bar1, 1); }
    __syncthreads();
    cluster_barrier();   // peer mbar init + zeroed h visible cluster-wide

    unsigned peer = rank ^ 1;
    unsigned stg0 = smem_u32(&stg[0][0]);
    unsigned stg1 = smem_u32(&stg[1][0]);
    unsigned peer_gr0 = mapa_rank(smem_u32(&gr[0][0]), peer);
    unsigned peer_gr1 = mapa_rank(smem_u32(&gr[1][0]), peer);
    unsigned peer_b0  = mapa_rank(bar0, peer);
    unsigned peer_b1  = mapa_rank(bar1, peer);

    float c0 = 0.f, c1 = 0.f;
    const size_t hrow0 = (size_t)b0 * L_OUT;
    const size_t hrow1 = (size_t)b1 * L_OUT;
    const float* xr0 = g_xpre + ((size_t)b0 * G4 + g) * XT;
    const float* xr1 = g_xpre + ((size_t)b1 * G4 + g) * XT;
    bool is_tanh_gate = (rank == 1) && (tid < HID);

    float4 xc0 = *(const float4*)(xr0);
    float4 xc1 = *(const float4*)(xr1);

    for (int t4 = 0; t4 < L_OUT; t4 += 4) {
        // prefetch next 4-step block (one ahead; XT padding covers the tail)
        float4 xn0 = *(const float4*)(xr0 + t4 + 4);
        float4 xn1 = *(const float4*)(xr1 + t4 + 4);

#pragma unroll
        for (int s = 0; s < 4; s++) {
            int t = t4 + s;
            float xp0 = (s == 0) ? xc0.x : (s == 1) ? xc0.y : (s == 2) ? xc0.z : xc0.w;
            float xp1 = (s == 0) ? xc1.x : (s == 1) ? xc1.y : (s == 2) ? xc1.z : xc1.w;

            // stream 0 dot
            unsigned long long a0 = pk2(0.f, 0.f), a1 = pk2(0.f, 0.f);
            unsigned long long a2 = pk2(0.f, 0.f), a3 = pk2(0.f, 0.f);
            {
                const ulonglong2* h2 = (const ulonglong2*)h_sh[0];
#pragma unroll
                for (int k = 0; k < 16; k++) {
                    ulonglong2 u = h2[2 * k];
                    ulonglong2 v = h2[2 * k + 1];
                    fma2(a0, w2[4 * k],     u.x);
                    fma2(a1, w2[4 * k + 1], u.y);
                    fma2(a2, w2[4 * k + 2], v.x);
                    fma2(a3, w2[4 * k + 3], v.y);
                }
            }
            float2 q0 = unpk2(a0), q1 = unpk2(a1), q2 = unpk2(a2), q3 = unpk2(a3);
            float pre0 = (((q0.x + q0.y) + (q1.x + q1.y)) +
                          ((q2.x + q2.y) + (q3.x + q3.y))) + xp0;

            // stream 1 dot (reuse accumulators)
            a0 = pk2(0.f, 0.f); a1 = pk2(0.f, 0.f);
            a2 = pk2(0.f, 0.f); a3 = pk2(0.f, 0.f);
            {
                const ulonglong2* h2 = (const ulonglong2*)h_sh[1];
#pragma unroll
                for (int k = 0; k < 16; k++) {
                    ulonglong2 u = h2[2 * k];
                    ulonglong2 v = h2[2 * k + 1];
                    fma2(a0, w2[4 * k],     u.x);
                    fma2(a1, w2[4 * k + 1], u.y);
                    fma2(a2, w2[4 * k + 2], v.x);
                    fma2(a3, w2[4 * k + 3], v.y);
                }
            }
            q0 = unpk2(a0); q1 = unpk2(a1); q2 = unpk2(a2); q3 = unpk2(a3);
            float pre1 = (((q0.x + q0.y) + (q1.x + q1.y)) +
                          ((q2.x + q2.y) + (q3.x + q3.y))) + xp1;

            float act0, act1;
            if (is_tanh_gate) { act0 = fast_tanh(pre0);    act1 = fast_tanh(pre1); }
            else              { act0 = fast_sigmoid(pre0); act1 = fast_sigmoid(pre1); }

            float* sb = stg[t & 1];
            sb[tid]       = act0;
            sb[256 + tid] = act1;
            __syncthreads();                // staging complete

            if (tid == 0) {
                unsigned lbar = (t & 1) ? bar1 : bar0;
                mbar_expect_tx(lbar, 2048); // both streams in one phase
                fence_proxy_async_cta();    // order STS -> async-proxy read
                bulk_copy_to_peer((t & 1) ? peer_gr1 : peer_gr0,
                                  (t & 1) ? stg1 : stg0,
                                  2048,
                                  (t & 1) ? peer_b1 : peer_b0);
            }

            if (tid < HID) {
                mbar_wait_cluster((t & 1) ? bar1 : bar0, (unsigned)((t >> 1) & 1));
                const float* own = stg[t & 1];
                const float* rem = gr[t & 1];
                float iv0, fv0, gv0, ov0, iv1, fv1, gv1, ov1;
                if (rank == 0) {
                    iv0 = own[tid];       fv0 = own[HID + tid];
                    gv0 = rem[tid];       ov0 = rem[HID + tid];
                    iv1 = own[256 + tid]; fv1 = own[256 + HID + tid];
                    gv1 = rem[256 + tid]; ov1 = rem[256 + HID + tid];
                } else {
                    gv0 = own[tid];       ov0 = own[HID + tid];
                    iv0 = rem[tid];       fv0 = rem[HID + tid];
                    gv1 = own[256 + tid]; ov1 = own[256 + HID + tid];
                    iv1 = rem[256 + tid]; fv1 = rem[256 + HID + tid];
                }
                c0 = fv0 * c0 + iv0 * gv0;
                c1 = fv1 * c1 + iv1 * gv1;
                float h0 = ov0 * fast_tanh(c0);
                float h1 = ov1 * fast_tanh(c1);
                h_sh[0][tid] = h0;
                h_sh[1][tid] = h1;
                if (rank == 0) {
                    g_hseq[(hrow0 + t) * HID + tid] = h0;
                    g_hseq[(hrow1 + t) * HID + tid] = h1;
                }
            }
            __syncthreads();   // h_sh(t) ready for next dot
        }
        xc0 = xn0; xc1 = xn1;
    }
    cluster_barrier();
}

// ---------------------------------------------------------------------------
// Kernel 5: readout.
// ---------------------------------------------------------------------------
__global__ void out_kernel(const float* __restrict__ out_w,
                           const float* __restrict__ out_b,
                           float* __restrict__ out) {
    __shared__ float h[HID];
    int b = blockIdx.x;
    if (threadIdx.x < HID)
        h[threadIdx.x] = g_hseq[((size_t)b * L_OUT + (L_OUT - 1)) * HID + threadIdx.x];
    __syncthreads();
    if (threadIdx.x < LBL) {
        float acc = out_b[threadIdx.x];
        const float* wr = out_w + (size_t)threadIdx.x * HID;
#pragma unroll 8
        for (int k = 0; k < HID; k++) acc += wr[k] * h[k];
        out[(size_t)b * LBL + threadIdx.x] = acc;
    }
}

// ---------------------------------------------------------------------------
// Launch
// ---------------------------------------------------------------------------
extern "C" void kernel_launch(void* const* d_in, const int* in_sizes, int n_in,
                              void* d_out, int out_size) {
    const float* inputs    = (const float*)d_in[0];
    const float* proj_w    = (const float*)d_in[4];
    const float* proj_b    = (const float*)d_in[5];
    const float* w_ih0     = (const float*)d_in[6];
    const float* w_hh0     = (const float*)d_in[7];
    const float* b_ih0     = (const float*)d_in[8];
    const float* b_hh0     = (const float*)d_in[9];
    const float* w_ih_rest = (const float*)d_in[10];
    const float* w_hh_rest = (const float*)d_in[11];
    const float* b_ih_rest = (const float*)d_in[12];
    const float* b_hh_rest = (const float*)d_in[13];
    const float* out_w     = (const float*)d_in[14];
    const float* out_b     = (const float*)d_in[15];
    float* out = (float*)d_out;

    combine_kernel<<<dim3(DIN / 32, G4 / 32), dim3(32, 32)>>>(proj_w, w_ih0);
    bias0_kernel<<<1, G4>>>(proj_b, w_ih0, b_ih0, b_hh0);

    xpre0_kernel<<<dim3((L_OUT + 127) / 128, G4 / 64, BATCH), 256>>>(inputs);

    scan_kernel<<<BATCH, 256>>>(w_hh0);   // 32 clusters x 2 CTAs, 2 batches each

    for (int l = 0; l < 3; l++) {
        gemm_ih_kernel<<<dim3((L_OUT + 63) / 64, G4 / 64, BATCH), 256>>>(
            w_ih_rest + (size_t)l * G4 * HID,
            b_ih_rest + (size_t)l * G4,
            b_hh_rest + (size_t)l * G4);
        scan_kernel<<<BATCH, 256>>>(w_hh_rest + (size_t)l * G4 * HID);
    }

    out_kernel<<<BATCH, 128>>>(out_w, out_b, out);
}